// round 14
// baseline (speedup 1.0000x reference)
#include <cuda_runtime.h>
#include <math.h>

#define NQ 10
#define DIMQ 1024
#define NL 2
#define WPB 8
#define NTHREADS (WPB * 32)

typedef unsigned long long u64;

// RY coefficients: (cos(theta/2), sin(theta/2)) per gate
__device__ float2 g_ry[NL * NQ];
// Factorized diagonal tables:
//  D_phi1 = zA1(lane) * zB1(r):   zA1[32] per-lane, zB1[16] lane-uniform packs
//  D_mid  = zAm(lane) * zBm[sel](r): sel = 2*par(lane&31) + par(lane&15)
// Pack layout: zB*[k] covers r = 2k (element 0) and r = 2k+1 (element 1):
//   .x = f32x2 cos pack, .y = f32x2 sin pack
__device__ float2 g_zA1[32];
__device__ float2 g_zAm[32];
__device__ ulonglong2 g_zB1[16];
__device__ ulonglong2 g_zBm[4][16];

// ---- f32x2 packed helpers ----
__device__ __forceinline__ u64 pk(float lo, float hi) {
    u64 r; asm("mov.b64 %0, {%1, %2};" : "=l"(r) : "f"(lo), "f"(hi)); return r;
}
__device__ __forceinline__ float2 upk(u64 v) {
    float lo, hi; asm("mov.b64 {%0, %1}, %2;" : "=f"(lo), "=f"(hi) : "l"(v));
    return make_float2(lo, hi);
}
__device__ __forceinline__ u64 fma2(u64 a, u64 b, u64 c) {
    u64 d; asm("fma.rn.f32x2 %0, %1, %2, %3;" : "=l"(d) : "l"(a), "l"(b), "l"(c)); return d;
}
__device__ __forceinline__ u64 mul2(u64 a, u64 b) {
    u64 d; asm("mul.rn.f32x2 %0, %1, %2;" : "=l"(d) : "l"(a), "l"(b)); return d;
}
__device__ __forceinline__ u64 add2(u64 a, u64 b) {
    u64 d; asm("add.rn.f32x2 %0, %1, %2;" : "=l"(d) : "l"(a), "l"(b)); return d;
}
__device__ __forceinline__ u64 sub2(u64 a, u64 b) {
    u64 d; asm("sub.rn.f32x2 %0, %1, %2;" : "=l"(d) : "l"(a), "l"(b)); return d;
}
__device__ __forceinline__ u64 swap64(u64 v) {
    float2 f = upk(v); return pk(f.y, f.x);
}
__device__ __forceinline__ u64 neg2(u64 v) {
    return v ^ 0x8000000080000000ull;   // sign-flip both f32 elements (alu pipe)
}
__device__ __forceinline__ int par(unsigned v) { return __popc(v) & 1; }
__host__ __device__ constexpr int parc(int v) {
    int p = 0;
    for (int i = 0; i < 10; i++) p ^= (v >> i) & 1;
    return p;
}

// ---- Prep: RY coeffs + factorized diagonal tables (128 threads, no syncs) ----
__global__ void prep_kernel(const float* __restrict__ w)
{
    const int t = threadIdx.x;

    if (t < NL * NQ) {
        float th = w[t * 3 + 1];
        g_ry[t] = make_float2(cosf(0.5f * th), sinf(0.5f * th));
    }

    if (t < 32) {
        // zA1: phi1 lane part. Wire q (0..4) -> lane bit (4-q).
        float a = 0.0f;
#pragma unroll
        for (int q = 0; q < 5; q++) {
            int bit = (t >> (4 - q)) & 1;
            a += (bit ? 0.5f : -0.5f) * w[q * 3 + 0];
        }
        g_zA1[t] = make_float2(cosf(a), sinf(a));

        // zAm: omega1 lane part + phi2 q=1..4 (lane-only parity masks).
        float am = 0.0f;
#pragma unroll
        for (int q = 0; q < 5; q++) {
            int bit = (t >> (4 - q)) & 1;
            am += (bit ? 0.5f : -0.5f) * w[q * 3 + 2];
        }
        const int rhoL[4] = {24, 28, 30, 31};   // q = 1..4 lane masks
#pragma unroll
        for (int j = 0; j < 4; j++) {
            int pb = __popc((unsigned)(t & rhoL[j])) & 1;
            am += (pb ? 0.5f : -0.5f) * w[(NQ + 1 + j) * 3 + 0];
        }
        g_zAm[t] = make_float2(cosf(am), sinf(am));
    }

    if (t < 16) {
        // zB1: phi1 reg part. Wire q (5..9) -> r bit (9-q).
        float c[2], s[2];
#pragma unroll
        for (int e = 0; e < 2; e++) {
            const int r = 2 * t + e;
            float b = 0.0f;
#pragma unroll
            for (int q = 5; q < 10; q++) {
                int bit = (r >> (9 - q)) & 1;
                b += (bit ? 0.5f : -0.5f) * w[q * 3 + 0];
            }
            c[e] = cosf(b); s[e] = sinf(b);
        }
        ulonglong2 v;
        v.x = pk(c[0], c[1]);
        v.y = pk(s[0], s[1]);
        g_zB1[t] = v;
    }

    if (t < 64) {
        // zBm[tbl][k]: omega1 reg part + phi2 q=5..9 (PL-conjugated) + phi2 q=0
        // (PL0-conjugated). tbl = 2*PL + PL0.
        const int tbl = t >> 4, k = t & 15;
        const int PL = tbl >> 1, PL0 = tbl & 1;
        const int rhoR[5] = {16, 24, 28, 30, 31};   // q = 5..9 reg masks
        float c[2], s[2];
#pragma unroll
        for (int e = 0; e < 2; e++) {
            const int r = 2 * k + e;
            float f = 0.0f;
#pragma unroll
            for (int q = 5; q < 10; q++) {
                int bit = (r >> (9 - q)) & 1;
                f += (bit ? 0.5f : -0.5f) * w[q * 3 + 2];
            }
#pragma unroll
            for (int j = 0; j < 5; j++) {
                int pb = (__popc((unsigned)(r & rhoR[j])) & 1) ^ PL;
                f += (pb ? 0.5f : -0.5f) * w[(NQ + 5 + j) * 3 + 0];
            }
            {
                int pb = (__popc((unsigned)(r & 31)) & 1) ^ PL0;
                f += (pb ? 0.5f : -0.5f) * w[NQ * 3 + 0];
            }
            c[e] = cosf(f); s[e] = sinf(f);
        }
        ulonglong2 v;
        v.x = pk(c[0], c[1]);
        v.y = pk(s[0], s[1]);
        g_zBm[tbl][k] = v;
    }
}

// Real-rotation butterfly over mask (LM lane bits, RM reg bits).
// role = par(lane&RHOL) ^ par(r&RHOR); role0: new = c*own - s*other;
// role1: new = c*own + s*other.
// Lane-gate path processes FOUR packs per step (16 SHFL.32 in flight).
template <int LM, int RM, int RHOL, int RHOR>
__device__ __forceinline__ void ry_p(u64* re, u64* im, int lane, float c, float s)
{
    const bool lp = (__popc(lane & RHOL) & 1) != 0;
    constexpr int flip = RHOR & 1;
    const float s00 = lp ? s : -s;                    // base parity 0, element 0
    const float s01 = (lp ^ (flip != 0)) ? s : -s;    // base parity 0, element 1
    const u64 C  = pk(c, c);
    const u64 S0 = pk(s00, s01);
    const u64 S1 = pk(-s00, -s01);                    // base parity 1 = negated roles

    constexpr int RMH = RM >> 1;   // pack-level xor
    constexpr int SW  = RM & 1;    // intra-pack element swap

    if (RMH == 0) {
#pragma unroll
        for (int k = 0; k < 16; k += 4) {
            u64 oR[4], oI[4];
#pragma unroll
            for (int j = 0; j < 4; j++) {
                u64 tR = re[k + j], tI = im[k + j];
                if (SW) { tR = swap64(tR); tI = swap64(tI); }
                if (LM != 0) {
                    tR = __shfl_xor_sync(0xffffffffu, tR, LM);
                    tI = __shfl_xor_sync(0xffffffffu, tI, LM);
                }
                oR[j] = tR; oI[j] = tI;
            }
#pragma unroll
            for (int j = 0; j < 4; j++) {
                const u64 S = parc((2 * (k + j)) & RHOR) ? S1 : S0;
                re[k + j] = fma2(S, oR[j], mul2(C, re[k + j]));
                im[k + j] = fma2(S, oI[j], mul2(C, im[k + j]));
            }
        }
    } else {
        constexpr int PB = RMH & (-RMH);
#pragma unroll
        for (int k0 = 0; k0 < 16; k0++) {
            if ((k0 & PB) == 0) {
                const int k1 = k0 ^ RMH;
                const u64 Sa = parc((2 * k0) & RHOR) ? S1 : S0;
                const u64 Sb = parc((2 * k1) & RHOR) ? S1 : S0;
                u64 v0R = re[k0], v0I = im[k0];
                u64 v1R = re[k1], v1I = im[k1];
                u64 o0R = v1R, o0I = v1I, o1R = v0R, o1I = v0I;
                if (SW) {
                    o0R = swap64(o0R); o0I = swap64(o0I);
                    o1R = swap64(o1R); o1I = swap64(o1I);
                }
                if (LM != 0) {
                    o0R = __shfl_xor_sync(0xffffffffu, o0R, LM);
                    o0I = __shfl_xor_sync(0xffffffffu, o0I, LM);
                    o1R = __shfl_xor_sync(0xffffffffu, o1R, LM);
                    o1I = __shfl_xor_sync(0xffffffffu, o1I, LM);
                }
                re[k0] = fma2(Sa, o0R, mul2(C, v0R));
                im[k0] = fma2(Sa, o0I, mul2(C, v0I));
                re[k1] = fma2(Sb, o1R, mul2(C, v1R));
                im[k1] = fma2(Sb, o1I, mul2(C, v1I));
            }
        }
    }
}

__global__ __launch_bounds__(NTHREADS, 2)
void qsim_reg_kernel(const float* __restrict__ x, float* __restrict__ out, int B)
{
    const int lane = threadIdx.x & 31;
    const int warp = threadIdx.x >> 5;
    const int b = blockIdx.x * WPB + warp;
    if (b >= B) return;

    u64 re[16], im[16];  // re[k] = (amp[2k].re, amp[2k+1].re) packed f32x2

    // ---- Load raw (normalization folded into RY1 gate 0) ----
    const ulonglong2* xb = (const ulonglong2*)(x + (size_t)b * DIMQ + lane * 32);
    u64 ssP = 0ull;
#pragma unroll
    for (int j = 0; j < 8; j++) {
        ulonglong2 v = xb[j];
        re[2 * j + 0] = v.x;
        re[2 * j + 1] = v.y;
        ssP = fma2(v.x, v.x, ssP);
        ssP = fma2(v.y, v.y, ssP);
    }
    float2 ssf = upk(ssP);
    float ss = ssf.x + ssf.y;
#pragma unroll
    for (int o = 16; o > 0; o >>= 1)
        ss += __shfl_xor_sync(0xffffffffu, ss, o);
    const float inv = rsqrtf(ss);

    // ---- D_phi1 on real state: (zA1(lane) * zB1(r)) * v ----
    {
        const float2 a1 = __ldg(&g_zA1[lane]);
        const u64 cA = pk(a1.x, a1.x);
        const u64 sA = pk(a1.y, a1.y);
        const u64 nsA = neg2(sA);
#pragma unroll
        for (int k = 0; k < 16; k++) {
            const ulonglong2 d = __ldg(&g_zB1[k]);   // lane-uniform: 1 wavefront
            const u64 v = re[k];
            const u64 tR = mul2(d.x, v);
            const u64 tI = mul2(d.y, v);
            re[k] = fma2(nsA, tI, mul2(cA, tR));
            im[k] = fma2(sA,  tR, mul2(cA, tI));
        }
    }

    // ---- RY layer 1 (gate 0 carries the normalization) ----
    {
        float2 g;
#define RG(i) g = __ldg(&g_ry[i])
        RG(0); ry_p<16, 0, 16,  0>(re, im, lane, g.x * inv, g.y * inv);  // lane
        RG(5); ry_p< 0,16,  0, 16>(re, im, lane, g.x, g.y);              // reg
        RG(1); ry_p< 8, 0,  8,  0>(re, im, lane, g.x, g.y);              // lane
        RG(6); ry_p< 0, 8,  0,  8>(re, im, lane, g.x, g.y);              // reg
        RG(2); ry_p< 4, 0,  4,  0>(re, im, lane, g.x, g.y);              // lane
        RG(7); ry_p< 0, 4,  0,  4>(re, im, lane, g.x, g.y);              // reg
        RG(3); ry_p< 2, 0,  2,  0>(re, im, lane, g.x, g.y);              // lane
        RG(8); ry_p< 0, 2,  0,  2>(re, im, lane, g.x, g.y);              // reg
        RG(4); ry_p< 1, 0,  1,  0>(re, im, lane, g.x, g.y);              // lane
        RG(9); ry_p< 0, 1,  0,  1>(re, im, lane, g.x, g.y);              // reg (elem swap)

        // ---- D_mid = zAm(lane) * zBm[2*PL+PL0](r), applied as two rotations ----
        {
            const int sel = 2 * par((unsigned)(lane & 31)) + par((unsigned)(lane & 15));
            const float2 am = __ldg(&g_zAm[lane]);
            const u64 cA = pk(am.x, am.x);
            const u64 sA = pk(am.y, am.y);
            const u64 nsA = neg2(sA);
            const ulonglong2* zbm = g_zBm[sel];
#pragma unroll
            for (int k = 0; k < 16; k++) {
                const ulonglong2 d = __ldg(&zbm[k]);  // lane-uniform per warp-group
                const u64 vR = re[k], vI = im[k];
                const u64 tR = fma2(neg2(d.y), vI, mul2(d.x, vR));
                const u64 tI = fma2(d.y,       vR, mul2(d.x, vI));
                re[k] = fma2(nsA, tI, mul2(cA, tR));
                im[k] = fma2(sA,  tR, mul2(cA, tI));
            }
        }

        // ---- RY layer 2 (CNOT-ring-1-absorbed masks/roles; verified round 4) ----
        RG(10); ry_p<24, 0, 15, 31>(re, im, lane, g.x, g.y);             // lane
        RG(15); ry_p< 0,24, 31, 16>(re, im, lane, g.x, g.y);             // reg
        RG(11); ry_p<12, 0, 24,  0>(re, im, lane, g.x, g.y);             // lane
        RG(16); ry_p< 0,12, 31, 24>(re, im, lane, g.x, g.y);             // reg
        RG(12); ry_p< 6, 0, 28,  0>(re, im, lane, g.x, g.y);             // lane
        RG(17); ry_p< 0, 6, 31, 28>(re, im, lane, g.x, g.y);             // reg
        RG(13); ry_p< 3, 0, 30,  0>(re, im, lane, g.x, g.y);             // lane
        RG(18); ry_p< 0, 3, 31, 30>(re, im, lane, g.x, g.y);             // reg
        RG(14); ry_p< 1,16, 31,  0>(re, im, lane, g.x, g.y);             // lane+reg
        RG(19); ry_p<24, 1, 31, 31>(re, im, lane, g.x, g.y);             // lane+elem
#undef RG
        // D_omega2: unit diagonal, |amp|^2 invariant -> dropped.
    }

    // ---- probs -> signed sums via 4-stage WHT over pack index ----
    u64 W[16];
#pragma unroll
    for (int k = 0; k < 16; k++)
        W[k] = fma2(re[k], re[k], mul2(im[k], im[k]));
#pragma unroll
    for (int s = 1; s < 16; s <<= 1) {
#pragma unroll
        for (int k = 0; k < 16; k++) {
            if ((k & s) == 0) {
                const u64 a = W[k], c = W[k | s];
                W[k] = add2(a, c);
                W[k | s] = sub2(a, c);
            }
        }
    }
    float av[10];
    {
        float2 w3  = upk(W[3]);
        float2 w9  = upk(W[9]);
        float2 w15 = upk(W[15]);
        float2 w0  = upk(W[0]);
        float2 w8  = upk(W[8]);
        float2 w6  = upk(W[6]);
        float2 w12 = upk(W[12]);
        av[0] = w3.x  + w3.y;    // Z_R=6
        av[1] = w9.x  - w9.y;    // Z_R=19
        av[2] = w15.x - w15.y;   // Z_R=31
        av[3] = w0.x  + w0.y;    // Z_R=0
        av[4] = av[2];           // Z_R=31
        av[5] = w8.x  + w8.y;    // Z_R=16
        av[6] = w3.x  - w3.y;    // Z_R=7
        av[7] = w6.x  + w6.y;    // Z_R=12
        av[8] = w12.x - w12.y;   // Z_R=25
        av[9] = av[1];           // Z_R=19
    }
#define SGNL(i, ZL) if (par((unsigned)(lane & (ZL)))) av[i] = -av[i];
    SGNL(0,  3)
    SGNL(1,  1)
    SGNL(2, 19)
    SGNL(3,  6)
    SGNL(4, 12)
    SGNL(5, 25)
    SGNL(6, 19)
    SGNL(7,  6)
    SGNL(8, 12)
    SGNL(9, 25)
#undef SGNL

    // ---- paired warp reduction (5 u64 lane-sums instead of 10 floats) ----
    u64 A[5];
#pragma unroll
    for (int j = 0; j < 5; j++) A[j] = pk(av[2 * j], av[2 * j + 1]);
#pragma unroll
    for (int o = 16; o > 0; o >>= 1) {
#pragma unroll
        for (int j = 0; j < 5; j++)
            A[j] = add2(A[j], __shfl_xor_sync(0xffffffffu, A[j], o));
    }
    if (lane < NQ) {
        float2 f = upk(A[lane >> 1]);
        out[(size_t)b * NQ + lane] = (lane & 1) ? f.y : f.x;
    }
}

extern "C" void kernel_launch(void* const* d_in, const int* in_sizes, int n_in,
                              void* d_out, int out_size)
{
    const float* x;
    const float* w;
    int xsize;
    if (in_sizes[0] == NL * NQ * 3) {
        w = (const float*)d_in[0];
        x = (const float*)d_in[1];
        xsize = in_sizes[1];
    } else {
        x = (const float*)d_in[0];
        w = (const float*)d_in[1];
        xsize = in_sizes[0];
    }
    const int B = xsize / DIMQ;
    float* out = (float*)d_out;
    prep_kernel<<<1, 128>>>(w);
    qsim_reg_kernel<<<(B + WPB - 1) / WPB, NTHREADS>>>(x, out, B);
    (void)n_in; (void)out_size;
}

// round 15
// speedup vs baseline: 1.0577x; 1.0577x over previous
#include <cuda_runtime.h>
#include <math.h>

#define NQ 10
#define DIMQ 1024
#define NL 2
#define WPB 4
#define NTHREADS (WPB * 32)

typedef unsigned long long u64;

// RY coefficients: (cos(theta/2), sin(theta/2)) per gate
__device__ float2 g_ry[NL * NQ];
// Packed diagonal tables, idx = k*32 + lane covering amps p0=lane*32+2k, p0+1.
// .x = f32x2 cos pack, .y = f32x2 sin pack
__device__ ulonglong2 g_d1[512];   // D_phi1
__device__ ulonglong2 g_dm[512];   // D_mid

// ---- f32x2 packed helpers ----
__device__ __forceinline__ u64 pk(float lo, float hi) {
    u64 r; asm("mov.b64 %0, {%1, %2};" : "=l"(r) : "f"(lo), "f"(hi)); return r;
}
__device__ __forceinline__ float2 upk(u64 v) {
    float lo, hi; asm("mov.b64 {%0, %1}, %2;" : "=f"(lo), "=f"(hi) : "l"(v));
    return make_float2(lo, hi);
}
__device__ __forceinline__ u64 fma2(u64 a, u64 b, u64 c) {
    u64 d; asm("fma.rn.f32x2 %0, %1, %2, %3;" : "=l"(d) : "l"(a), "l"(b), "l"(c)); return d;
}
__device__ __forceinline__ u64 mul2(u64 a, u64 b) {
    u64 d; asm("mul.rn.f32x2 %0, %1, %2;" : "=l"(d) : "l"(a), "l"(b)); return d;
}
__device__ __forceinline__ u64 add2(u64 a, u64 b) {
    u64 d; asm("add.rn.f32x2 %0, %1, %2;" : "=l"(d) : "l"(a), "l"(b)); return d;
}
__device__ __forceinline__ u64 sub2(u64 a, u64 b) {
    u64 d; asm("sub.rn.f32x2 %0, %1, %2;" : "=l"(d) : "l"(a), "l"(b)); return d;
}
__device__ __forceinline__ u64 swap64(u64 v) {
    float2 f = upk(v); return pk(f.y, f.x);
}
__device__ __forceinline__ u64 neg2(u64 v) {
    return v ^ 0x8000000080000000ull;   // sign-flip both f32 elements (alu pipe)
}
__device__ __forceinline__ int par(unsigned v) { return __popc(v) & 1; }
__host__ __device__ constexpr int parc(int v) {
    int p = 0;
    for (int i = 0; i < 10; i++) p ^= (v >> i) & 1;
    return p;
}

// ---- Prep: RY coeffs + diagonal tables ----
__global__ void prep_kernel(const float* __restrict__ w)
{
    __shared__ float cA[DIMQ], sA[DIMQ];
    const int t = threadIdx.x;

    if (t < NL * NQ) {
        float th = w[t * 3 + 1];
        g_ry[t] = make_float2(cosf(0.5f * th), sinf(0.5f * th));
    }

    // D_phi1: angle(p) = sum_q (bit_q(p) ? +0.5 : -0.5) * phi1_q, wire q -> bit 9-q
    {
        float a = 0.0f;
#pragma unroll
        for (int q = 0; q < NQ; q++) {
            int bit = (t >> (9 - q)) & 1;
            a += (bit ? 0.5f : -0.5f) * w[q * 3 + 0];
        }
        cA[t] = cosf(a); sA[t] = sinf(a);
    }
    __syncthreads();
    if (t < 512) {
        const int lane = t & 31, k = t >> 5;
        const int p0 = lane * 32 + 2 * k;
        ulonglong2 v;
        v.x = pk(cA[p0], cA[p0 + 1]);
        v.y = pk(sA[p0], sA[p0 + 1]);
        g_d1[t] = v;
    }
    __syncthreads();

    // D_mid = D_omega1 (plain bits) * D_phi2 (rho parity masks from CNOT-ring-1)
    {
        const int rho[10] = {511, 768, 896, 960, 992, 1008, 1016, 1020, 1022, 1023};
        float a = 0.0f;
#pragma unroll
        for (int q = 0; q < NQ; q++) {
            int bit = (t >> (9 - q)) & 1;
            a += (bit ? 0.5f : -0.5f) * w[q * 3 + 2];
        }
#pragma unroll
        for (int q = 0; q < NQ; q++) {
            int pb = __popc(t & rho[q]) & 1;
            a += (pb ? 0.5f : -0.5f) * w[(NQ + q) * 3 + 0];
        }
        cA[t] = cosf(a); sA[t] = sinf(a);
    }
    __syncthreads();
    if (t < 512) {
        const int lane = t & 31, k = t >> 5;
        const int p0 = lane * 32 + 2 * k;
        ulonglong2 v;
        v.x = pk(cA[p0], cA[p0 + 1]);
        v.y = pk(sA[p0], sA[p0 + 1]);
        g_dm[t] = v;
    }
}

// Real-rotation butterfly over mask (LM lane bits, RM reg bits).
// role = par(lane&RHOL) ^ par(r&RHOR); role0: new = c*own - s*other;
// role1: new = c*own + s*other.
// Lane-gate path processes FOUR packs per step (16 SHFL.32 in flight).
template <int LM, int RM, int RHOL, int RHOR>
__device__ __forceinline__ void ry_p(u64* re, u64* im, int lane, float c, float s)
{
    const bool lp = (__popc(lane & RHOL) & 1) != 0;
    constexpr int flip = RHOR & 1;
    const float s00 = lp ? s : -s;                    // base parity 0, element 0
    const float s01 = (lp ^ (flip != 0)) ? s : -s;    // base parity 0, element 1
    const u64 C  = pk(c, c);
    const u64 S0 = pk(s00, s01);
    const u64 S1 = pk(-s00, -s01);                    // base parity 1 = negated roles

    constexpr int RMH = RM >> 1;   // pack-level xor
    constexpr int SW  = RM & 1;    // intra-pack element swap

    if (RMH == 0) {
#pragma unroll
        for (int k = 0; k < 16; k += 4) {
            u64 oR[4], oI[4];
#pragma unroll
            for (int j = 0; j < 4; j++) {
                u64 tR = re[k + j], tI = im[k + j];
                if (SW) { tR = swap64(tR); tI = swap64(tI); }
                if (LM != 0) {
                    tR = __shfl_xor_sync(0xffffffffu, tR, LM);
                    tI = __shfl_xor_sync(0xffffffffu, tI, LM);
                }
                oR[j] = tR; oI[j] = tI;
            }
#pragma unroll
            for (int j = 0; j < 4; j++) {
                const u64 S = parc((2 * (k + j)) & RHOR) ? S1 : S0;
                re[k + j] = fma2(S, oR[j], mul2(C, re[k + j]));
                im[k + j] = fma2(S, oI[j], mul2(C, im[k + j]));
            }
        }
    } else {
        constexpr int PB = RMH & (-RMH);
#pragma unroll
        for (int k0 = 0; k0 < 16; k0++) {
            if ((k0 & PB) == 0) {
                const int k1 = k0 ^ RMH;
                const u64 Sa = parc((2 * k0) & RHOR) ? S1 : S0;
                const u64 Sb = parc((2 * k1) & RHOR) ? S1 : S0;
                u64 v0R = re[k0], v0I = im[k0];
                u64 v1R = re[k1], v1I = im[k1];
                u64 o0R = v1R, o0I = v1I, o1R = v0R, o1I = v0I;
                if (SW) {
                    o0R = swap64(o0R); o0I = swap64(o0I);
                    o1R = swap64(o1R); o1I = swap64(o1I);
                }
                if (LM != 0) {
                    o0R = __shfl_xor_sync(0xffffffffu, o0R, LM);
                    o0I = __shfl_xor_sync(0xffffffffu, o0I, LM);
                    o1R = __shfl_xor_sync(0xffffffffu, o1R, LM);
                    o1I = __shfl_xor_sync(0xffffffffu, o1I, LM);
                }
                re[k0] = fma2(Sa, o0R, mul2(C, v0R));
                im[k0] = fma2(Sa, o0I, mul2(C, v0I));
                re[k1] = fma2(Sb, o1R, mul2(C, v1R));
                im[k1] = fma2(Sb, o1I, mul2(C, v1I));
            }
        }
    }
}

__global__ __launch_bounds__(NTHREADS, 4)
void qsim_reg_kernel(const float* __restrict__ x, float* __restrict__ out, int B)
{
    const int lane = threadIdx.x & 31;
    const int warp = threadIdx.x >> 5;
    const int b = blockIdx.x * WPB + warp;
    if (b >= B) return;

    u64 re[16], im[16];  // re[k] = (amp[2k].re, amp[2k+1].re) packed f32x2

    // ---- Load raw (normalization folded into RY1 gate 0) ----
    const ulonglong2* xb = (const ulonglong2*)(x + (size_t)b * DIMQ + lane * 32);
    u64 ssP = 0ull;
#pragma unroll
    for (int j = 0; j < 8; j++) {
        ulonglong2 v = xb[j];
        re[2 * j + 0] = v.x;
        re[2 * j + 1] = v.y;
        ssP = fma2(v.x, v.x, ssP);
        ssP = fma2(v.y, v.y, ssP);
    }
    float2 ssf = upk(ssP);
    float ss = ssf.x + ssf.y;
#pragma unroll
    for (int o = 16; o > 0; o >>= 1)
        ss += __shfl_xor_sync(0xffffffffu, ss, o);
    const float inv = rsqrtf(ss);

    // ---- D_phi1 on real state: im = sin*v, re = cos*v ----
#pragma unroll
    for (int k = 0; k < 16; k++) {
        const ulonglong2 d = __ldg(&g_d1[k * 32 + lane]);
        const u64 v = re[k];
        re[k] = mul2(d.x, v);
        im[k] = mul2(d.y, v);
    }

    // ---- RY layer 1 (gate 0 carries the normalization) ----
    {
        float2 g;
#define RG(i) g = __ldg(&g_ry[i])
        RG(0); ry_p<16, 0, 16,  0>(re, im, lane, g.x * inv, g.y * inv);  // lane
        RG(5); ry_p< 0,16,  0, 16>(re, im, lane, g.x, g.y);              // reg
        RG(1); ry_p< 8, 0,  8,  0>(re, im, lane, g.x, g.y);              // lane
        RG(6); ry_p< 0, 8,  0,  8>(re, im, lane, g.x, g.y);              // reg
        RG(2); ry_p< 4, 0,  4,  0>(re, im, lane, g.x, g.y);              // lane
        RG(7); ry_p< 0, 4,  0,  4>(re, im, lane, g.x, g.y);              // reg
        RG(3); ry_p< 2, 0,  2,  0>(re, im, lane, g.x, g.y);              // lane
        RG(8); ry_p< 0, 2,  0,  2>(re, im, lane, g.x, g.y);              // reg
        RG(4); ry_p< 1, 0,  1,  0>(re, im, lane, g.x, g.y);              // lane
        RG(9); ry_p< 0, 1,  0,  1>(re, im, lane, g.x, g.y);              // reg (elem swap)

        // ---- D_mid = D_omega1 * D_phi2 (complex unit diagonal); -sin via XOR ----
#pragma unroll
        for (int k = 0; k < 16; k++) {
            const ulonglong2 d = __ldg(&g_dm[k * 32 + lane]);
            const u64 vR = re[k], vI = im[k];
            re[k] = fma2(neg2(d.y), vI, mul2(d.x, vR));
            im[k] = fma2(d.y,       vR, mul2(d.x, vI));
        }

        // ---- RY layer 2 (CNOT-ring-1-absorbed masks/roles; verified round 4) ----
        RG(10); ry_p<24, 0, 15, 31>(re, im, lane, g.x, g.y);             // lane
        RG(15); ry_p< 0,24, 31, 16>(re, im, lane, g.x, g.y);             // reg
        RG(11); ry_p<12, 0, 24,  0>(re, im, lane, g.x, g.y);             // lane
        RG(16); ry_p< 0,12, 31, 24>(re, im, lane, g.x, g.y);             // reg
        RG(12); ry_p< 6, 0, 28,  0>(re, im, lane, g.x, g.y);             // lane
        RG(17); ry_p< 0, 6, 31, 28>(re, im, lane, g.x, g.y);             // reg
        RG(13); ry_p< 3, 0, 30,  0>(re, im, lane, g.x, g.y);             // lane
        RG(18); ry_p< 0, 3, 31, 30>(re, im, lane, g.x, g.y);             // reg
        RG(14); ry_p< 1,16, 31,  0>(re, im, lane, g.x, g.y);             // lane+reg
        RG(19); ry_p<24, 1, 31, 31>(re, im, lane, g.x, g.y);             // lane+elem
#undef RG
        // D_omega2: unit diagonal, |amp|^2 invariant -> dropped.
    }

    // ---- probs -> signed sums via 4-stage WHT over pack index ----
    u64 W[16];
#pragma unroll
    for (int k = 0; k < 16; k++)
        W[k] = fma2(re[k], re[k], mul2(im[k], im[k]));
#pragma unroll
    for (int s = 1; s < 16; s <<= 1) {
#pragma unroll
        for (int k = 0; k < 16; k++) {
            if ((k & s) == 0) {
                const u64 a = W[k], c = W[k | s];
                W[k] = add2(a, c);
                W[k | s] = sub2(a, c);
            }
        }
    }
    float av[10];
    {
        float2 w3  = upk(W[3]);
        float2 w9  = upk(W[9]);
        float2 w15 = upk(W[15]);
        float2 w0  = upk(W[0]);
        float2 w8  = upk(W[8]);
        float2 w6  = upk(W[6]);
        float2 w12 = upk(W[12]);
        av[0] = w3.x  + w3.y;    // Z_R=6
        av[1] = w9.x  - w9.y;    // Z_R=19
        av[2] = w15.x - w15.y;   // Z_R=31
        av[3] = w0.x  + w0.y;    // Z_R=0
        av[4] = av[2];           // Z_R=31
        av[5] = w8.x  + w8.y;    // Z_R=16
        av[6] = w3.x  - w3.y;    // Z_R=7
        av[7] = w6.x  + w6.y;    // Z_R=12
        av[8] = w12.x - w12.y;   // Z_R=25
        av[9] = av[1];           // Z_R=19
    }
#define SGNL(i, ZL) if (par((unsigned)(lane & (ZL)))) av[i] = -av[i];
    SGNL(0,  3)
    SGNL(1,  1)
    SGNL(2, 19)
    SGNL(3,  6)
    SGNL(4, 12)
    SGNL(5, 25)
    SGNL(6, 19)
    SGNL(7,  6)
    SGNL(8, 12)
    SGNL(9, 25)
#undef SGNL

    // ---- paired warp reduction (5 u64 lane-sums instead of 10 floats) ----
    u64 A[5];
#pragma unroll
    for (int j = 0; j < 5; j++) A[j] = pk(av[2 * j], av[2 * j + 1]);
#pragma unroll
    for (int o = 16; o > 0; o >>= 1) {
#pragma unroll
        for (int j = 0; j < 5; j++)
            A[j] = add2(A[j], __shfl_xor_sync(0xffffffffu, A[j], o));
    }
    if (lane < NQ) {
        float2 f = upk(A[lane >> 1]);
        out[(size_t)b * NQ + lane] = (lane & 1) ? f.y : f.x;
    }
}

extern "C" void kernel_launch(void* const* d_in, const int* in_sizes, int n_in,
                              void* d_out, int out_size)
{
    const float* x;
    const float* w;
    int xsize;
    if (in_sizes[0] == NL * NQ * 3) {
        w = (const float*)d_in[0];
        x = (const float*)d_in[1];
        xsize = in_sizes[1];
    } else {
        x = (const float*)d_in[0];
        w = (const float*)d_in[1];
        xsize = in_sizes[0];
    }
    const int B = xsize / DIMQ;
    float* out = (float*)d_out;
    prep_kernel<<<1, DIMQ>>>(w);
    qsim_reg_kernel<<<(B + WPB - 1) / WPB, NTHREADS>>>(x, out, B);
    (void)n_in; (void)out_size;
}

// round 16
// speedup vs baseline: 1.0613x; 1.0035x over previous
#include <cuda_runtime.h>
#include <math.h>

#define NQ 10
#define DIMQ 1024
#define NL 2
#define WPB 2
#define NTHREADS (WPB * 32)

typedef unsigned long long u64;

// RY coefficients: (cos(theta/2), sin(theta/2)) per gate
__device__ float2 g_ry[NL * NQ];
// Packed diagonal tables, idx = k*32 + lane covering amps p0=lane*32+2k, p0+1.
// .x = f32x2 cos pack, .y = f32x2 sin pack
__device__ ulonglong2 g_d1[512];   // D_phi1
__device__ ulonglong2 g_dm[512];   // D_mid

// ---- f32x2 packed helpers ----
__device__ __forceinline__ u64 pk(float lo, float hi) {
    u64 r; asm("mov.b64 %0, {%1, %2};" : "=l"(r) : "f"(lo), "f"(hi)); return r;
}
__device__ __forceinline__ float2 upk(u64 v) {
    float lo, hi; asm("mov.b64 {%0, %1}, %2;" : "=f"(lo), "=f"(hi) : "l"(v));
    return make_float2(lo, hi);
}
__device__ __forceinline__ u64 fma2(u64 a, u64 b, u64 c) {
    u64 d; asm("fma.rn.f32x2 %0, %1, %2, %3;" : "=l"(d) : "l"(a), "l"(b), "l"(c)); return d;
}
__device__ __forceinline__ u64 mul2(u64 a, u64 b) {
    u64 d; asm("mul.rn.f32x2 %0, %1, %2;" : "=l"(d) : "l"(a), "l"(b)); return d;
}
__device__ __forceinline__ u64 add2(u64 a, u64 b) {
    u64 d; asm("add.rn.f32x2 %0, %1, %2;" : "=l"(d) : "l"(a), "l"(b)); return d;
}
__device__ __forceinline__ u64 sub2(u64 a, u64 b) {
    u64 d; asm("sub.rn.f32x2 %0, %1, %2;" : "=l"(d) : "l"(a), "l"(b)); return d;
}
__device__ __forceinline__ u64 swap64(u64 v) {
    float2 f = upk(v); return pk(f.y, f.x);
}
__device__ __forceinline__ u64 neg2(u64 v) {
    return v ^ 0x8000000080000000ull;   // sign-flip both f32 elements (alu pipe)
}
__device__ __forceinline__ int par(unsigned v) { return __popc(v) & 1; }
__host__ __device__ constexpr int parc(int v) {
    int p = 0;
    for (int i = 0; i < 10; i++) p ^= (v >> i) & 1;
    return p;
}

// ---- Prep: RY coeffs + diagonal tables ----
__global__ void prep_kernel(const float* __restrict__ w)
{
    __shared__ float cA[DIMQ], sA[DIMQ];
    const int t = threadIdx.x;

    if (t < NL * NQ) {
        float th = w[t * 3 + 1];
        g_ry[t] = make_float2(cosf(0.5f * th), sinf(0.5f * th));
    }

    // D_phi1: angle(p) = sum_q (bit_q(p) ? +0.5 : -0.5) * phi1_q, wire q -> bit 9-q
    {
        float a = 0.0f;
#pragma unroll
        for (int q = 0; q < NQ; q++) {
            int bit = (t >> (9 - q)) & 1;
            a += (bit ? 0.5f : -0.5f) * w[q * 3 + 0];
        }
        cA[t] = cosf(a); sA[t] = sinf(a);
    }
    __syncthreads();
    if (t < 512) {
        const int lane = t & 31, k = t >> 5;
        const int p0 = lane * 32 + 2 * k;
        ulonglong2 v;
        v.x = pk(cA[p0], cA[p0 + 1]);
        v.y = pk(sA[p0], sA[p0 + 1]);
        g_d1[t] = v;
    }
    __syncthreads();

    // D_mid = D_omega1 (plain bits) * D_phi2 (rho parity masks from CNOT-ring-1)
    {
        const int rho[10] = {511, 768, 896, 960, 992, 1008, 1016, 1020, 1022, 1023};
        float a = 0.0f;
#pragma unroll
        for (int q = 0; q < NQ; q++) {
            int bit = (t >> (9 - q)) & 1;
            a += (bit ? 0.5f : -0.5f) * w[q * 3 + 2];
        }
#pragma unroll
        for (int q = 0; q < NQ; q++) {
            int pb = __popc(t & rho[q]) & 1;
            a += (pb ? 0.5f : -0.5f) * w[(NQ + q) * 3 + 0];
        }
        cA[t] = cosf(a); sA[t] = sinf(a);
    }
    __syncthreads();
    if (t < 512) {
        const int lane = t & 31, k = t >> 5;
        const int p0 = lane * 32 + 2 * k;
        ulonglong2 v;
        v.x = pk(cA[p0], cA[p0 + 1]);
        v.y = pk(sA[p0], sA[p0 + 1]);
        g_dm[t] = v;
    }
}

// Real-rotation butterfly over mask (LM lane bits, RM reg bits).
// role = par(lane&RHOL) ^ par(r&RHOR); role0: new = c*own - s*other;
// role1: new = c*own + s*other.
// Lane-gate path processes FOUR packs per step (16 SHFL.32 in flight).
template <int LM, int RM, int RHOL, int RHOR>
__device__ __forceinline__ void ry_p(u64* re, u64* im, int lane, float c, float s)
{
    const bool lp = (__popc(lane & RHOL) & 1) != 0;
    constexpr int flip = RHOR & 1;
    const float s00 = lp ? s : -s;                    // base parity 0, element 0
    const float s01 = (lp ^ (flip != 0)) ? s : -s;    // base parity 0, element 1
    const u64 C  = pk(c, c);
    const u64 S0 = pk(s00, s01);
    const u64 S1 = pk(-s00, -s01);                    // base parity 1 = negated roles

    constexpr int RMH = RM >> 1;   // pack-level xor
    constexpr int SW  = RM & 1;    // intra-pack element swap

    if (RMH == 0) {
#pragma unroll
        for (int k = 0; k < 16; k += 4) {
            u64 oR[4], oI[4];
#pragma unroll
            for (int j = 0; j < 4; j++) {
                u64 tR = re[k + j], tI = im[k + j];
                if (SW) { tR = swap64(tR); tI = swap64(tI); }
                if (LM != 0) {
                    tR = __shfl_xor_sync(0xffffffffu, tR, LM);
                    tI = __shfl_xor_sync(0xffffffffu, tI, LM);
                }
                oR[j] = tR; oI[j] = tI;
            }
#pragma unroll
            for (int j = 0; j < 4; j++) {
                const u64 S = parc((2 * (k + j)) & RHOR) ? S1 : S0;
                re[k + j] = fma2(S, oR[j], mul2(C, re[k + j]));
                im[k + j] = fma2(S, oI[j], mul2(C, im[k + j]));
            }
        }
    } else {
        constexpr int PB = RMH & (-RMH);
#pragma unroll
        for (int k0 = 0; k0 < 16; k0++) {
            if ((k0 & PB) == 0) {
                const int k1 = k0 ^ RMH;
                const u64 Sa = parc((2 * k0) & RHOR) ? S1 : S0;
                const u64 Sb = parc((2 * k1) & RHOR) ? S1 : S0;
                u64 v0R = re[k0], v0I = im[k0];
                u64 v1R = re[k1], v1I = im[k1];
                u64 o0R = v1R, o0I = v1I, o1R = v0R, o1I = v0I;
                if (SW) {
                    o0R = swap64(o0R); o0I = swap64(o0I);
                    o1R = swap64(o1R); o1I = swap64(o1I);
                }
                if (LM != 0) {
                    o0R = __shfl_xor_sync(0xffffffffu, o0R, LM);
                    o0I = __shfl_xor_sync(0xffffffffu, o0I, LM);
                    o1R = __shfl_xor_sync(0xffffffffu, o1R, LM);
                    o1I = __shfl_xor_sync(0xffffffffu, o1I, LM);
                }
                re[k0] = fma2(Sa, o0R, mul2(C, v0R));
                im[k0] = fma2(Sa, o0I, mul2(C, v0I));
                re[k1] = fma2(Sb, o1R, mul2(C, v1R));
                im[k1] = fma2(Sb, o1I, mul2(C, v1I));
            }
        }
    }
}

__global__ __launch_bounds__(NTHREADS, 8)
void qsim_reg_kernel(const float* __restrict__ x, float* __restrict__ out, int B)
{
    const int lane = threadIdx.x & 31;
    const int warp = threadIdx.x >> 5;
    const int b = blockIdx.x * WPB + warp;
    if (b >= B) return;

    u64 re[16], im[16];  // re[k] = (amp[2k].re, amp[2k+1].re) packed f32x2

    // ---- Load raw (normalization folded into RY1 gate 0) ----
    const ulonglong2* xb = (const ulonglong2*)(x + (size_t)b * DIMQ + lane * 32);
    u64 ssP = 0ull;
#pragma unroll
    for (int j = 0; j < 8; j++) {
        ulonglong2 v = xb[j];
        re[2 * j + 0] = v.x;
        re[2 * j + 1] = v.y;
        ssP = fma2(v.x, v.x, ssP);
        ssP = fma2(v.y, v.y, ssP);
    }
    float2 ssf = upk(ssP);
    float ss = ssf.x + ssf.y;
#pragma unroll
    for (int o = 16; o > 0; o >>= 1)
        ss += __shfl_xor_sync(0xffffffffu, ss, o);
    const float inv = rsqrtf(ss);

    // ---- D_phi1 on real state: im = sin*v, re = cos*v ----
#pragma unroll
    for (int k = 0; k < 16; k++) {
        const ulonglong2 d = __ldg(&g_d1[k * 32 + lane]);
        const u64 v = re[k];
        re[k] = mul2(d.x, v);
        im[k] = mul2(d.y, v);
    }

    // ---- RY layer 1 (gate 0 carries the normalization) ----
    {
        float2 g;
#define RG(i) g = __ldg(&g_ry[i])
        RG(0); ry_p<16, 0, 16,  0>(re, im, lane, g.x * inv, g.y * inv);  // lane
        RG(5); ry_p< 0,16,  0, 16>(re, im, lane, g.x, g.y);              // reg
        RG(1); ry_p< 8, 0,  8,  0>(re, im, lane, g.x, g.y);              // lane
        RG(6); ry_p< 0, 8,  0,  8>(re, im, lane, g.x, g.y);              // reg
        RG(2); ry_p< 4, 0,  4,  0>(re, im, lane, g.x, g.y);              // lane
        RG(7); ry_p< 0, 4,  0,  4>(re, im, lane, g.x, g.y);              // reg
        RG(3); ry_p< 2, 0,  2,  0>(re, im, lane, g.x, g.y);              // lane
        RG(8); ry_p< 0, 2,  0,  2>(re, im, lane, g.x, g.y);              // reg
        RG(4); ry_p< 1, 0,  1,  0>(re, im, lane, g.x, g.y);              // lane
        RG(9); ry_p< 0, 1,  0,  1>(re, im, lane, g.x, g.y);              // reg (elem swap)

        // ---- D_mid = D_omega1 * D_phi2 (complex unit diagonal); -sin via XOR ----
#pragma unroll
        for (int k = 0; k < 16; k++) {
            const ulonglong2 d = __ldg(&g_dm[k * 32 + lane]);
            const u64 vR = re[k], vI = im[k];
            re[k] = fma2(neg2(d.y), vI, mul2(d.x, vR));
            im[k] = fma2(d.y,       vR, mul2(d.x, vI));
        }

        // ---- RY layer 2 (CNOT-ring-1-absorbed masks/roles; verified round 4) ----
        RG(10); ry_p<24, 0, 15, 31>(re, im, lane, g.x, g.y);             // lane
        RG(15); ry_p< 0,24, 31, 16>(re, im, lane, g.x, g.y);             // reg
        RG(11); ry_p<12, 0, 24,  0>(re, im, lane, g.x, g.y);             // lane
        RG(16); ry_p< 0,12, 31, 24>(re, im, lane, g.x, g.y);             // reg
        RG(12); ry_p< 6, 0, 28,  0>(re, im, lane, g.x, g.y);             // lane
        RG(17); ry_p< 0, 6, 31, 28>(re, im, lane, g.x, g.y);             // reg
        RG(13); ry_p< 3, 0, 30,  0>(re, im, lane, g.x, g.y);             // lane
        RG(18); ry_p< 0, 3, 31, 30>(re, im, lane, g.x, g.y);             // reg
        RG(14); ry_p< 1,16, 31,  0>(re, im, lane, g.x, g.y);             // lane+reg
        RG(19); ry_p<24, 1, 31, 31>(re, im, lane, g.x, g.y);             // lane+elem
#undef RG
        // D_omega2: unit diagonal, |amp|^2 invariant -> dropped.
    }

    // ---- probs -> signed sums via 4-stage WHT over pack index ----
    u64 W[16];
#pragma unroll
    for (int k = 0; k < 16; k++)
        W[k] = fma2(re[k], re[k], mul2(im[k], im[k]));
#pragma unroll
    for (int s = 1; s < 16; s <<= 1) {
#pragma unroll
        for (int k = 0; k < 16; k++) {
            if ((k & s) == 0) {
                const u64 a = W[k], c = W[k | s];
                W[k] = add2(a, c);
                W[k | s] = sub2(a, c);
            }
        }
    }
    float av[10];
    {
        float2 w3  = upk(W[3]);
        float2 w9  = upk(W[9]);
        float2 w15 = upk(W[15]);
        float2 w0  = upk(W[0]);
        float2 w8  = upk(W[8]);
        float2 w6  = upk(W[6]);
        float2 w12 = upk(W[12]);
        av[0] = w3.x  + w3.y;    // Z_R=6
        av[1] = w9.x  - w9.y;    // Z_R=19
        av[2] = w15.x - w15.y;   // Z_R=31
        av[3] = w0.x  + w0.y;    // Z_R=0
        av[4] = av[2];           // Z_R=31
        av[5] = w8.x  + w8.y;    // Z_R=16
        av[6] = w3.x  - w3.y;    // Z_R=7
        av[7] = w6.x  + w6.y;    // Z_R=12
        av[8] = w12.x - w12.y;   // Z_R=25
        av[9] = av[1];           // Z_R=19
    }
#define SGNL(i, ZL) if (par((unsigned)(lane & (ZL)))) av[i] = -av[i];
    SGNL(0,  3)
    SGNL(1,  1)
    SGNL(2, 19)
    SGNL(3,  6)
    SGNL(4, 12)
    SGNL(5, 25)
    SGNL(6, 19)
    SGNL(7,  6)
    SGNL(8, 12)
    SGNL(9, 25)
#undef SGNL

    // ---- paired warp reduction (5 u64 lane-sums instead of 10 floats) ----
    u64 A[5];
#pragma unroll
    for (int j = 0; j < 5; j++) A[j] = pk(av[2 * j], av[2 * j + 1]);
#pragma unroll
    for (int o = 16; o > 0; o >>= 1) {
#pragma unroll
        for (int j = 0; j < 5; j++)
            A[j] = add2(A[j], __shfl_xor_sync(0xffffffffu, A[j], o));
    }
    if (lane < NQ) {
        float2 f = upk(A[lane >> 1]);
        out[(size_t)b * NQ + lane] = (lane & 1) ? f.y : f.x;
    }
}

extern "C" void kernel_launch(void* const* d_in, const int* in_sizes, int n_in,
                              void* d_out, int out_size)
{
    const float* x;
    const float* w;
    int xsize;
    if (in_sizes[0] == NL * NQ * 3) {
        w = (const float*)d_in[0];
        x = (const float*)d_in[1];
        xsize = in_sizes[1];
    } else {
        x = (const float*)d_in[0];
        w = (const float*)d_in[1];
        xsize = in_sizes[0];
    }
    const int B = xsize / DIMQ;
    float* out = (float*)d_out;
    prep_kernel<<<1, DIMQ>>>(w);
    qsim_reg_kernel<<<(B + WPB - 1) / WPB, NTHREADS>>>(x, out, B);
    (void)n_in; (void)out_size;
}